// round 3
// baseline (speedup 1.0000x reference)
#include <cuda_runtime.h>
#include <cuda_bf16.h>
#include <cstdint>

// Problem constants
#define NN 100000
#define NE 1600000
#define NG 256

// ---------------- scratch (device globals; no runtime allocation) ----------------
__device__ float g_bufA[(size_t)NN * 128];   // xl (linear transform output)
__device__ float g_bufB[(size_t)NN * 128];   // agg (neighbor aggregation)
__device__ float g_bufC[(size_t)NN * 128];   // h (activation output)
__device__ float g_deg[NN];
__device__ float g_isq[NN];
__device__ float g_inv[NN];
__device__ float g_sums[NG * 64];
__device__ float g_cnt[NG];

// ---------------- helpers ----------------
__device__ __forceinline__ float gelu_tanh(float x) {
    // jax.nn.gelu(approximate=True)
    const float c = 0.7978845608028654f;   // sqrt(2/pi)
    float x3 = x * x * x;
    return 0.5f * x * (1.0f + tanhf(c * (x + 0.044715f * x3)));
}

__device__ __forceinline__ void red_add_v4(float* p, float a, float b, float c, float d) {
    asm volatile("red.global.add.v4.f32 [%0], {%1,%2,%3,%4};"
                 :: "l"(p), "f"(a), "f"(b), "f"(c), "f"(d) : "memory");
}

// ---------------- kernels ----------------
__global__ void k_zero(float* __restrict__ p, int n4) {
    int i = blockIdx.x * blockDim.x + threadIdx.x;
    if (i < n4) reinterpret_cast<float4*>(p)[i] = make_float4(0.f, 0.f, 0.f, 0.f);
}

__global__ void k_deg_init(float* __restrict__ deg) {
    int i = blockIdx.x * blockDim.x + threadIdx.x;
    if (i < NN) deg[i] = 1.0f;   // self-loop
}

__global__ void k_deg_count(const int* __restrict__ dst, float* __restrict__ deg) {
    int e = blockIdx.x * blockDim.x + threadIdx.x;
    if (e < NE) atomicAdd(&deg[dst[e]], 1.0f);
}

__global__ void k_deg_fin(const float* __restrict__ deg, float* __restrict__ isq,
                          float* __restrict__ inv) {
    int i = blockIdx.x * blockDim.x + threadIdx.x;
    if (i < NN) {
        float d = deg[i];
        isq[i] = rsqrtf(d);
        inv[i] = 1.0f / d;
    }
}

// Y[n, COUT] = X[n, 128] @ W[128, COUT]
// block: COUT threads, 32 rows per block. W staged in SMEM, x tile in SMEM (broadcast reads).
template <int COUT>
__global__ void k_gemm(const float* __restrict__ X, const float* __restrict__ W,
                       float* __restrict__ Y, int n) {
    extern __shared__ float sm[];
    float* sW = sm;                  // [128 * COUT]
    float* sX = sm + 128 * COUT;     // [32 * 128]
    const int c = threadIdx.x;
    const int row0 = blockIdx.x * 32;

    // load W column c (coalesced across threads per k)
    #pragma unroll 8
    for (int k = 0; k < 128; k++) sW[k * COUT + c] = W[k * COUT + c];

    // load x tile (float4)
    const int NV = 32 * 32;  // 32 rows * 32 float4
    for (int i = c; i < NV; i += COUT) {
        int r = i >> 5, v = i & 31;
        float4 val = make_float4(0.f, 0.f, 0.f, 0.f);
        if (row0 + r < n) val = reinterpret_cast<const float4*>(X)[(size_t)(row0 + r) * 32 + v];
        reinterpret_cast<float4*>(sX)[i] = val;
    }
    __syncthreads();

    float acc[32];
    #pragma unroll
    for (int r = 0; r < 32; r++) acc[r] = 0.f;

    #pragma unroll 4
    for (int k = 0; k < 128; k++) {
        float w = sW[k * COUT + c];
        #pragma unroll
        for (int r = 0; r < 32; r++) acc[r] += sX[r * 128 + k] * w;
    }

    #pragma unroll
    for (int r = 0; r < 32; r++) {
        if (row0 + r < n) Y[(size_t)(row0 + r) * COUT + c] = acc[r];
    }
}

// agg[dst] += isq[src]*isq[dst] * xl[src]   (C/4 threads per edge, v4 reductions)
template <int C>
__global__ void k_edge(const int* __restrict__ src, const int* __restrict__ dst,
                       const float* __restrict__ isq, const float* __restrict__ xl,
                       float* __restrict__ agg) {
    const int TPE = C / 4;
    long long tid = (long long)blockIdx.x * blockDim.x + threadIdx.x;
    long long e = tid / TPE;
    int v = (int)(tid % TPE);
    if (e >= NE) return;
    int s = __ldg(&src[e]);
    int d = __ldg(&dst[e]);
    float nrm = __ldg(&isq[s]) * __ldg(&isq[d]);
    float4 x = reinterpret_cast<const float4*>(xl)[(size_t)s * TPE + v];
    float* p = agg + (size_t)d * C + (size_t)v * 4;
    red_add_v4(p, nrm * x.x, nrm * x.y, nrm * x.z, nrm * x.w);
}

// h = gelu(agg + deg_inv * xl + b)
template <int C>
__global__ void k_node(const float* __restrict__ agg, const float* __restrict__ xl,
                       const float* __restrict__ b, const float* __restrict__ inv,
                       float* __restrict__ h) {
    const int TPN = C / 4;
    int i = blockIdx.x * blockDim.x + threadIdx.x;
    if (i >= NN * TPN) return;
    int node = i / TPN;
    int v = i % TPN;
    float iv = inv[node];
    float4 a = reinterpret_cast<const float4*>(agg)[i];
    float4 x = reinterpret_cast<const float4*>(xl)[i];
    float4 bb = reinterpret_cast<const float4*>(b)[v];
    float4 r;
    r.x = gelu_tanh(a.x + iv * x.x + bb.x);
    r.y = gelu_tanh(a.y + iv * x.y + bb.y);
    r.z = gelu_tanh(a.z + iv * x.z + bb.z);
    r.w = gelu_tanh(a.w + iv * x.w + bb.w);
    reinterpret_cast<float4*>(h)[i] = r;
}

__global__ void k_pool_count(const int* __restrict__ batch, float* __restrict__ cnt) {
    int i = blockIdx.x * blockDim.x + threadIdx.x;
    if (i < NN) atomicAdd(&cnt[batch[i]], 1.0f);
}

__global__ void k_pool_sum(const int* __restrict__ batch, const float* __restrict__ h,
                           float* __restrict__ sums) {
    int i = blockIdx.x * blockDim.x + threadIdx.x;   // over NN*16 (64/4)
    if (i >= NN * 16) return;
    int node = i / 16;
    int v = i % 16;
    int g = __ldg(&batch[node]);
    float4 x = reinterpret_cast<const float4*>(h)[i];
    float* p = sums + (size_t)g * 64 + (size_t)v * 4;
    red_add_v4(p, x.x, x.y, x.z, x.w);
}

__global__ void k_pool_fin(const float* __restrict__ sums, const float* __restrict__ cnt,
                           float* __restrict__ out) {
    int i = blockIdx.x * blockDim.x + threadIdx.x;
    if (i >= NG * 64) return;
    float c = fmaxf(cnt[i / 64], 1.0f);
    out[i] = sums[i] / c;
}

// ---------------- launch ----------------
extern "C" void kernel_launch(void* const* d_in, const int* in_sizes, int n_in,
                              void* d_out, int out_size) {
    const float* x = (const float*)d_in[0];
    const int* ei = (const int*)d_in[1];      // int32 (JAX x64 disabled)
    const int* batch = (const int*)d_in[2];
    const float* W0 = (const float*)d_in[3];
    const float* b0 = (const float*)d_in[4];
    const float* W1 = (const float*)d_in[5];
    const float* b1 = (const float*)d_in[6];
    const float* W2 = (const float*)d_in[7];
    const float* b2 = (const float*)d_in[8];
    const int* src = ei;
    const int* dst = ei + NE;

    float *bufA, *bufB, *bufC, *deg, *isq, *inv, *sums, *cnt;
    cudaGetSymbolAddress((void**)&bufA, g_bufA);
    cudaGetSymbolAddress((void**)&bufB, g_bufB);
    cudaGetSymbolAddress((void**)&bufC, g_bufC);
    cudaGetSymbolAddress((void**)&deg, g_deg);
    cudaGetSymbolAddress((void**)&isq, g_isq);
    cudaGetSymbolAddress((void**)&inv, g_inv);
    cudaGetSymbolAddress((void**)&sums, g_sums);
    cudaGetSymbolAddress((void**)&cnt, g_cnt);

    const int SMEM128 = (128 * 128 + 32 * 128) * 4;  // 81920
    const int SMEM64  = (128 * 64 + 32 * 128) * 4;   // 49152
    cudaFuncSetAttribute(k_gemm<128>, cudaFuncAttributeMaxDynamicSharedMemorySize, SMEM128);
    cudaFuncSetAttribute(k_gemm<64>, cudaFuncAttributeMaxDynamicSharedMemorySize, SMEM64);

    // degrees
    k_deg_init<<<(NN + 255) / 256, 256>>>(deg);
    k_deg_count<<<(NE + 255) / 256, 256>>>(dst, deg);
    k_deg_fin<<<(NN + 255) / 256, 256>>>(deg, isq, inv);

    const int GB = (NN + 31) / 32;  // gemm blocks
    const long long ET128 = (long long)NE * 32;
    const long long ET64 = (long long)NE * 16;

    // ---- layer 0: x -> bufA(xl) -> bufB(agg) -> bufC(h) ----
    k_gemm<128><<<GB, 128, SMEM128>>>(x, W0, bufA, NN);
    k_zero<<<(NN * 32 + 255) / 256, 256>>>(bufB, NN * 32);
    k_edge<128><<<(int)((ET128 + 255) / 256), 256>>>(src, dst, isq, bufA, bufB);
    k_node<128><<<(NN * 32 + 255) / 256, 256>>>(bufB, bufA, b0, inv, bufC);

    // ---- layer 1 ----
    k_gemm<128><<<GB, 128, SMEM128>>>(bufC, W1, bufA, NN);
    k_zero<<<(NN * 32 + 255) / 256, 256>>>(bufB, NN * 32);
    k_edge<128><<<(int)((ET128 + 255) / 256), 256>>>(src, dst, isq, bufA, bufB);
    k_node<128><<<(NN * 32 + 255) / 256, 256>>>(bufB, bufA, b1, inv, bufC);

    // ---- layer 2 (C=64) ----
    k_gemm<64><<<GB, 64, SMEM64>>>(bufC, W2, bufA, NN);
    k_zero<<<(NN * 16 + 255) / 256, 256>>>(bufB, NN * 16);
    k_edge<64><<<(int)((ET64 + 255) / 256), 256>>>(src, dst, isq, bufA, bufB);
    k_node<64><<<(NN * 16 + 255) / 256, 256>>>(bufB, bufA, b2, inv, bufC);

    // ---- pooling ----
    k_zero<<<(NG * 16 + 255) / 256, 256>>>(sums, NG * 16);  // 256*64/4
    k_zero<<<1, 64>>>(cnt, NG / 4);
    k_pool_count<<<(NN + 255) / 256, 256>>>(batch, cnt);
    k_pool_sum<<<(NN * 16 + 255) / 256, 256>>>(batch, bufC, sums);
    k_pool_fin<<<(NG * 64 + 255) / 256, 256>>>(sums, cnt, (float*)d_out);
}

// round 4
// speedup vs baseline: 2.2416x; 2.2416x over previous
#include <cuda_runtime.h>
#include <cstdint>

#define NN 100000
#define NE 1600000
#define NG 256
#define SCAN_NB 98   // ceil(100000/1024)

// ---------------- device scratch ----------------
__device__ float g_bufA[(size_t)NN * 128];   // xls = isq * (x@W)
__device__ float g_bufC[(size_t)NN * 128];   // h
__device__ float g_isq[NN];
__device__ int   g_cnti[NN];
__device__ int   g_fill[NN];
__device__ int   g_rowptr[NN + 1];
__device__ int   g_tmp[NN];
__device__ int   g_part[SCAN_NB + 2];
__device__ int   g_offs[SCAN_NB + 2];
__device__ int   g_csr[NE];
__device__ float g_sums[NG * 64];
__device__ float g_cntf[NG];

// ---------------- helpers ----------------
__device__ __forceinline__ float gelu_tanh(float x) {
    const float c = 0.7978845608028654f;
    float x3 = x * x * x;
    return 0.5f * x * (1.0f + tanhf(c * (x + 0.044715f * x3)));
}

__device__ __forceinline__ float tf32r(float x) {
    uint32_t u;
    asm("cvt.rna.tf32.f32 %0, %1;" : "=r"(u) : "f"(x));
    return __uint_as_float(u);
}

__device__ __forceinline__ void mma_tf32(float4& d, const uint32_t a[4], const uint32_t b[2]) {
    asm volatile(
        "mma.sync.aligned.m16n8k8.row.col.f32.tf32.tf32.f32 "
        "{%0,%1,%2,%3},{%4,%5,%6,%7},{%8,%9},{%0,%1,%2,%3};"
        : "+f"(d.x), "+f"(d.y), "+f"(d.z), "+f"(d.w)
        : "r"(a[0]), "r"(a[1]), "r"(a[2]), "r"(a[3]), "r"(b[0]), "r"(b[1]));
}

__device__ __forceinline__ void red_add_v4(float* p, float a, float b, float c, float d) {
    asm volatile("red.global.add.v4.f32 [%0], {%1,%2,%3,%4};"
                 :: "l"(p), "f"(a), "f"(b), "f"(c), "f"(d) : "memory");
}

// ---------------- degree / CSR build ----------------
__global__ void k_count(const int* __restrict__ dst, int* __restrict__ cnt) {
    int e = blockIdx.x * blockDim.x + threadIdx.x;
    if (e < NE) atomicAdd(&cnt[dst[e]], 1);
}

__global__ void k_isq(const int* __restrict__ cnt, float* __restrict__ isq) {
    int i = blockIdx.x * blockDim.x + threadIdx.x;
    if (i < NN) isq[i] = rsqrtf((float)cnt[i] + 1.0f);
}

__global__ void k_scan1(const int* __restrict__ cnt, int* __restrict__ tmp,
                        int* __restrict__ part) {
    __shared__ int sm[1024];
    int i = blockIdx.x * 1024 + threadIdx.x;
    int v = (i < NN) ? cnt[i] : 0;
    sm[threadIdx.x] = v;
    __syncthreads();
    for (int off = 1; off < 1024; off <<= 1) {
        int t = (threadIdx.x >= off) ? sm[threadIdx.x - off] : 0;
        __syncthreads();
        sm[threadIdx.x] += t;
        __syncthreads();
    }
    if (i < NN) tmp[i] = sm[threadIdx.x];   // inclusive
    if (threadIdx.x == 1023) part[blockIdx.x] = sm[1023];
}

__global__ void k_scan2(const int* __restrict__ part, int* __restrict__ offs) {
    if (threadIdx.x == 0) {
        int run = 0;
        for (int b = 0; b < SCAN_NB; b++) { offs[b] = run; run += part[b]; }
    }
}

__global__ void k_scan3(const int* __restrict__ tmp, const int* __restrict__ offs,
                        int* __restrict__ rowptr) {
    int i = blockIdx.x * blockDim.x + threadIdx.x;
    if (i < NN) rowptr[i + 1] = tmp[i] + offs[i >> 10];
    if (i == 0) rowptr[0] = 0;
}

__global__ void k_fill(const int* __restrict__ src, const int* __restrict__ dst,
                       const int* __restrict__ rowptr, int* __restrict__ fill,
                       int* __restrict__ csr) {
    int e = blockIdx.x * blockDim.x + threadIdx.x;
    if (e >= NE) return;
    int d = dst[e];
    int pos = rowptr[d] + atomicAdd(&fill[d], 1);
    csr[pos] = src[e];
}

// ---------------- TF32 tensor-core GEMM: Y[r] = s[r] * (X[r,:128] @ W[:128,COUT]) ----------------
template <int COUT>
__global__ __launch_bounds__(256) void k_gemm_tc(
    const float* __restrict__ X, const float* __restrict__ W,
    const float* __restrict__ s, float* __restrict__ Y, int n) {
    constexpr int WS = (COUT == 128) ? 132 : 68;
    constexpr int NT = COUT / 8;
    extern __shared__ float smx[];
    float* sX = smx;              // [128][132]
    float* sW = smx + 128 * 132;  // [128][WS]
    int tid = threadIdx.x, lane = tid & 31, warp = tid >> 5;
    int row0 = blockIdx.x * 128;

    // X tile (tf32-rounded)
    for (int i = tid; i < 128 * 32; i += 256) {
        int r = i >> 5, v = i & 31;
        float4 val = make_float4(0.f, 0.f, 0.f, 0.f);
        if (row0 + r < n) val = __ldg(&((const float4*)X)[(size_t)(row0 + r) * 32 + v]);
        val.x = tf32r(val.x); val.y = tf32r(val.y);
        val.z = tf32r(val.z); val.w = tf32r(val.w);
        *(float4*)&sX[r * 132 + v * 4] = val;
    }
    // W (tf32-rounded)
    for (int i = tid; i < 128 * (COUT / 4); i += 256) {
        int k = i / (COUT / 4), c4 = i % (COUT / 4);
        float4 wv = __ldg(&((const float4*)W)[(size_t)k * (COUT / 4) + c4]);
        wv.x = tf32r(wv.x); wv.y = tf32r(wv.y);
        wv.z = tf32r(wv.z); wv.w = tf32r(wv.w);
        *(float4*)&sW[k * WS + c4 * 4] = wv;
    }
    __syncthreads();

    float4 acc[NT];
    #pragma unroll
    for (int t = 0; t < NT; t++) acc[t] = make_float4(0.f, 0.f, 0.f, 0.f);
    int qid = lane >> 2, tq = lane & 3;
    int rw = warp * 16;

    #pragma unroll
    for (int kt = 0; kt < 16; kt++) {
        int k0 = kt * 8;
        uint32_t a[4];
        a[0] = __float_as_uint(sX[(rw + qid) * 132 + k0 + tq]);
        a[1] = __float_as_uint(sX[(rw + qid + 8) * 132 + k0 + tq]);
        a[2] = __float_as_uint(sX[(rw + qid) * 132 + k0 + tq + 4]);
        a[3] = __float_as_uint(sX[(rw + qid + 8) * 132 + k0 + tq + 4]);
        #pragma unroll
        for (int nt = 0; nt < NT; nt++) {
            uint32_t bb[2];
            bb[0] = __float_as_uint(sW[(k0 + tq) * WS + nt * 8 + qid]);
            bb[1] = __float_as_uint(sW[(k0 + tq + 4) * WS + nt * 8 + qid]);
            mma_tf32(acc[nt], a, bb);
        }
    }

    int r1 = row0 + rw + qid, r2 = r1 + 8;
    float s1v = (r1 < n) ? __ldg(&s[r1]) : 0.f;
    float s2v = (r2 < n) ? __ldg(&s[r2]) : 0.f;
    #pragma unroll
    for (int nt = 0; nt < NT; nt++) {
        int c = nt * 8 + 2 * tq;
        if (r1 < n) *(float2*)&Y[(size_t)r1 * COUT + c] = make_float2(s1v * acc[nt].x, s1v * acc[nt].y);
        if (r2 < n) *(float2*)&Y[(size_t)r2 * COUT + c] = make_float2(s2v * acc[nt].z, s2v * acc[nt].w);
    }
}

// ---------------- fused edge gather + node epilogue ----------------
// h[i] = gelu( isq[i] * (sum_{j in N(i)} xls[j] + xls[i]) + b )
__global__ void k_edgenode128(const int* __restrict__ rp, const int* __restrict__ csr,
                              const float* __restrict__ isq, const float* __restrict__ xls,
                              const float* __restrict__ b, float* __restrict__ h) {
    int w = (blockIdx.x * blockDim.x + threadIdx.x) >> 5;
    int lane = threadIdx.x & 31;
    if (w >= NN) return;
    int e0 = __ldg(&rp[w]), e1 = __ldg(&rp[w + 1]);
    const float4* X4 = (const float4*)xls;
    float4 acc = __ldg(&X4[(size_t)w * 32 + lane]);   // self term
    int e = e0;
    for (; e + 2 <= e1; e += 2) {
        int s0 = __ldg(&csr[e]), s1 = __ldg(&csr[e + 1]);
        float4 v0 = __ldg(&X4[(size_t)s0 * 32 + lane]);
        float4 v1 = __ldg(&X4[(size_t)s1 * 32 + lane]);
        acc.x += v0.x + v1.x; acc.y += v0.y + v1.y;
        acc.z += v0.z + v1.z; acc.w += v0.w + v1.w;
    }
    if (e < e1) {
        int s0 = __ldg(&csr[e]);
        float4 v0 = __ldg(&X4[(size_t)s0 * 32 + lane]);
        acc.x += v0.x; acc.y += v0.y; acc.z += v0.z; acc.w += v0.w;
    }
    float sc = __ldg(&isq[w]);
    float4 bb = __ldg(&((const float4*)b)[lane]);
    float4 r;
    r.x = gelu_tanh(sc * acc.x + bb.x);
    r.y = gelu_tanh(sc * acc.y + bb.y);
    r.z = gelu_tanh(sc * acc.z + bb.z);
    r.w = gelu_tanh(sc * acc.w + bb.w);
    ((float4*)h)[(size_t)w * 32 + lane] = r;
}

__global__ void k_edgenode64(const int* __restrict__ rp, const int* __restrict__ csr,
                             const float* __restrict__ isq, const float* __restrict__ xls,
                             const float* __restrict__ b, float* __restrict__ h) {
    int t = blockIdx.x * blockDim.x + threadIdx.x;
    int node = t >> 4;
    int lane = t & 15;
    if (node >= NN) return;
    int e0 = __ldg(&rp[node]), e1 = __ldg(&rp[node + 1]);
    const float4* X4 = (const float4*)xls;
    float4 acc = __ldg(&X4[(size_t)node * 16 + lane]);
    int e = e0;
    for (; e + 2 <= e1; e += 2) {
        int s0 = __ldg(&csr[e]), s1 = __ldg(&csr[e + 1]);
        float4 v0 = __ldg(&X4[(size_t)s0 * 16 + lane]);
        float4 v1 = __ldg(&X4[(size_t)s1 * 16 + lane]);
        acc.x += v0.x + v1.x; acc.y += v0.y + v1.y;
        acc.z += v0.z + v1.z; acc.w += v0.w + v1.w;
    }
    if (e < e1) {
        int s0 = __ldg(&csr[e]);
        float4 v0 = __ldg(&X4[(size_t)s0 * 16 + lane]);
        acc.x += v0.x; acc.y += v0.y; acc.z += v0.z; acc.w += v0.w;
    }
    float sc = __ldg(&isq[node]);
    float4 bb = __ldg(&((const float4*)b)[lane]);
    float4 r;
    r.x = gelu_tanh(sc * acc.x + bb.x);
    r.y = gelu_tanh(sc * acc.y + bb.y);
    r.z = gelu_tanh(sc * acc.z + bb.z);
    r.w = gelu_tanh(sc * acc.w + bb.w);
    ((float4*)h)[(size_t)node * 16 + lane] = r;
}

// ---------------- pooling ----------------
__global__ void k_pool_count(const int* __restrict__ batch, float* __restrict__ cnt) {
    int i = blockIdx.x * blockDim.x + threadIdx.x;
    if (i < NN) atomicAdd(&cnt[batch[i]], 1.0f);
}

__global__ void k_pool_sum(const int* __restrict__ batch, const float* __restrict__ h,
                           float* __restrict__ sums) {
    int i = blockIdx.x * blockDim.x + threadIdx.x;
    if (i >= NN * 16) return;
    int node = i >> 4;
    int v = i & 15;
    int g = __ldg(&batch[node]);
    float4 x = ((const float4*)h)[i];
    red_add_v4(sums + (size_t)g * 64 + (size_t)v * 4, x.x, x.y, x.z, x.w);
}

__global__ void k_pool_fin(const float* __restrict__ sums, const float* __restrict__ cnt,
                           float* __restrict__ out) {
    int i = blockIdx.x * blockDim.x + threadIdx.x;
    if (i >= NG * 64) return;
    float c = fmaxf(cnt[i >> 6], 1.0f);
    out[i] = sums[i] / c;
}

// ---------------- launch ----------------
extern "C" void kernel_launch(void* const* d_in, const int* in_sizes, int n_in,
                              void* d_out, int out_size) {
    const float* x = (const float*)d_in[0];
    const int* ei = (const int*)d_in[1];
    const int* batch = (const int*)d_in[2];
    const float* W0 = (const float*)d_in[3];
    const float* b0 = (const float*)d_in[4];
    const float* W1 = (const float*)d_in[5];
    const float* b1 = (const float*)d_in[6];
    const float* W2 = (const float*)d_in[7];
    const float* b2 = (const float*)d_in[8];
    const int* src = ei;
    const int* dst = ei + NE;

    float *bufA, *bufC, *isq, *sums, *cntf;
    int *cnti, *fill, *rowptr, *tmp, *part, *offs, *csr;
    cudaGetSymbolAddress((void**)&bufA, g_bufA);
    cudaGetSymbolAddress((void**)&bufC, g_bufC);
    cudaGetSymbolAddress((void**)&isq, g_isq);
    cudaGetSymbolAddress((void**)&cnti, g_cnti);
    cudaGetSymbolAddress((void**)&fill, g_fill);
    cudaGetSymbolAddress((void**)&rowptr, g_rowptr);
    cudaGetSymbolAddress((void**)&tmp, g_tmp);
    cudaGetSymbolAddress((void**)&part, g_part);
    cudaGetSymbolAddress((void**)&offs, g_offs);
    cudaGetSymbolAddress((void**)&csr, g_csr);
    cudaGetSymbolAddress((void**)&sums, g_sums);
    cudaGetSymbolAddress((void**)&cntf, g_cntf);

    const int SM128 = (128 * 132 + 128 * 132) * 4;  // 135168
    const int SM64  = (128 * 132 + 128 * 68) * 4;   // 102400
    static bool attr_set = false;
    cudaFuncSetAttribute(k_gemm_tc<128>, cudaFuncAttributeMaxDynamicSharedMemorySize, SM128);
    cudaFuncSetAttribute(k_gemm_tc<64>, cudaFuncAttributeMaxDynamicSharedMemorySize, SM64);
    (void)attr_set;

    // CSR build + degrees
    cudaMemsetAsync(cnti, 0, NN * sizeof(int));
    k_count<<<(NE + 255) / 256, 256>>>(dst, cnti);
    k_isq<<<(NN + 255) / 256, 256>>>(cnti, isq);
    k_scan1<<<SCAN_NB, 1024>>>(cnti, tmp, part);
    k_scan2<<<1, 32>>>(part, offs);
    k_scan3<<<(NN + 255) / 256, 256>>>(tmp, offs, rowptr);
    cudaMemsetAsync(fill, 0, NN * sizeof(int));
    k_fill<<<(NE + 255) / 256, 256>>>(src, dst, rowptr, fill, csr);

    const int GB = (NN + 127) / 128;

    // layer 0
    k_gemm_tc<128><<<GB, 256, SM128>>>(x, W0, isq, bufA, NN);
    k_edgenode128<<<(NN * 32 + 255) / 256, 256>>>(rowptr, csr, isq, bufA, b0, bufC);
    // layer 1
    k_gemm_tc<128><<<GB, 256, SM128>>>(bufC, W1, isq, bufA, NN);
    k_edgenode128<<<(NN * 32 + 255) / 256, 256>>>(rowptr, csr, isq, bufA, b1, bufC);
    // layer 2 (out 64)
    k_gemm_tc<64><<<GB, 256, SM64>>>(bufC, W2, isq, bufA, NN);
    k_edgenode64<<<(NN * 16 + 255) / 256, 256>>>(rowptr, csr, isq, bufA, b2, bufC);

    // pooling
    cudaMemsetAsync(sums, 0, NG * 64 * sizeof(float));
    cudaMemsetAsync(cntf, 0, NG * sizeof(float));
    k_pool_count<<<(NN + 255) / 256, 256>>>(batch, cntf);
    k_pool_sum<<<(NN * 16 + 255) / 256, 256>>>(batch, bufC, sums);
    k_pool_fin<<<(NG * 64 + 255) / 256, 256>>>(sums, cntf, (float*)d_out);
}

// round 5
// speedup vs baseline: 2.4587x; 1.0969x over previous
#include <cuda_runtime.h>
#include <cuda_fp16.h>
#include <cstdint>

#define NN 100000
#define NE 1600000
#define NG 256
#define SCAN_NB 98   // ceil(100000/1024)

// ---------------- device scratch ----------------
__device__ __half g_msg[(size_t)NN * 128];   // xls = isq * (x@W), fp16
__device__ float  g_bufC[(size_t)NN * 128];  // h (fp32, GEMM input)
__device__ float  g_isq[NN];
__device__ int    g_cnti[NN];
__device__ int    g_fill[NN];
__device__ int    g_rowptr[NN + 1];
__device__ int    g_tmp[NN];
__device__ int    g_part[SCAN_NB + 2];
__device__ int    g_offs[SCAN_NB + 2];
__device__ int    g_csr[NE];
__device__ float  g_sums[NG * 64];
__device__ float  g_cntf[NG];

// ---------------- helpers ----------------
__device__ __forceinline__ float gelu_tanh(float x) {
    const float c = 0.7978845608028654f;
    float x3 = x * x * x;
    return 0.5f * x * (1.0f + tanhf(c * (x + 0.044715f * x3)));
}

__device__ __forceinline__ float tf32r(float x) {
    uint32_t u;
    asm("cvt.rna.tf32.f32 %0, %1;" : "=r"(u) : "f"(x));
    return __uint_as_float(u);
}

__device__ __forceinline__ void mma_tf32(float4& d, const uint32_t a[4], const uint32_t b[2]) {
    asm volatile(
        "mma.sync.aligned.m16n8k8.row.col.f32.tf32.tf32.f32 "
        "{%0,%1,%2,%3},{%4,%5,%6,%7},{%8,%9},{%0,%1,%2,%3};"
        : "+f"(d.x), "+f"(d.y), "+f"(d.z), "+f"(d.w)
        : "r"(a[0]), "r"(a[1]), "r"(a[2]), "r"(a[3]), "r"(b[0]), "r"(b[1]));
}

__device__ __forceinline__ void red_add_v4(float* p, float a, float b, float c, float d) {
    asm volatile("red.global.add.v4.f32 [%0], {%1,%2,%3,%4};"
                 :: "l"(p), "f"(a), "f"(b), "f"(c), "f"(d) : "memory");
}

__device__ __forceinline__ void acc_h2x2(float4& acc, uint2 v) {
    float2 lo = __half22float2(*reinterpret_cast<__half2*>(&v.x));
    float2 hi = __half22float2(*reinterpret_cast<__half2*>(&v.y));
    acc.x += lo.x; acc.y += lo.y; acc.z += hi.x; acc.w += hi.y;
}

// ---------------- degree / CSR build ----------------
__global__ void k_count(const int* __restrict__ dst, int* __restrict__ cnt) {
    int e = blockIdx.x * blockDim.x + threadIdx.x;
    if (e < NE) atomicAdd(&cnt[dst[e]], 1);
}

__global__ void k_isq(const int* __restrict__ cnt, float* __restrict__ isq) {
    int i = blockIdx.x * blockDim.x + threadIdx.x;
    if (i < NN) isq[i] = rsqrtf((float)cnt[i] + 1.0f);
}

__global__ void k_scan1(const int* __restrict__ cnt, int* __restrict__ tmp,
                        int* __restrict__ part) {
    __shared__ int sm[1024];
    int i = blockIdx.x * 1024 + threadIdx.x;
    int v = (i < NN) ? cnt[i] : 0;
    sm[threadIdx.x] = v;
    __syncthreads();
    for (int off = 1; off < 1024; off <<= 1) {
        int t = (threadIdx.x >= off) ? sm[threadIdx.x - off] : 0;
        __syncthreads();
        sm[threadIdx.x] += t;
        __syncthreads();
    }
    if (i < NN) tmp[i] = sm[threadIdx.x];   // inclusive
    if (threadIdx.x == 1023) part[blockIdx.x] = sm[1023];
}

__global__ void k_scan2(const int* __restrict__ part, int* __restrict__ offs) {
    __shared__ int sm[128];
    int t = threadIdx.x;
    sm[t] = (t < SCAN_NB) ? part[t] : 0;
    __syncthreads();
    #pragma unroll
    for (int off = 1; off < 128; off <<= 1) {
        int v = (t >= off) ? sm[t - off] : 0;
        __syncthreads();
        sm[t] += v;
        __syncthreads();
    }
    // exclusive
    if (t < SCAN_NB) offs[t] = (t == 0) ? 0 : sm[t - 1];
}

__global__ void k_scan3(const int* __restrict__ tmp, const int* __restrict__ offs,
                        int* __restrict__ rowptr) {
    int i = blockIdx.x * blockDim.x + threadIdx.x;
    if (i < NN) rowptr[i + 1] = tmp[i] + offs[i >> 10];
    if (i == 0) rowptr[0] = 0;
}

__global__ void k_fill(const int* __restrict__ src, const int* __restrict__ dst,
                       const int* __restrict__ rowptr, int* __restrict__ fill,
                       int* __restrict__ csr) {
    int e = blockIdx.x * blockDim.x + threadIdx.x;
    if (e >= NE) return;
    int d = dst[e];
    int pos = rowptr[d] + atomicAdd(&fill[d], 1);
    csr[pos] = src[e];
}

// ---------------- TF32 tensor-core GEMM: Y[r] = fp16( s[r] * (X[r,:128] @ W[:128,COUT]) ) ----------------
template <int COUT>
__global__ __launch_bounds__(256) void k_gemm_tc(
    const float* __restrict__ X, const float* __restrict__ W,
    const float* __restrict__ s, __half* __restrict__ Y, int n) {
    constexpr int WS = (COUT == 128) ? 132 : 68;
    constexpr int NT = COUT / 8;
    extern __shared__ float smx[];
    float* sX = smx;              // [128][132]
    float* sW = smx + 128 * 132;  // [128][WS]
    int tid = threadIdx.x, lane = tid & 31, warp = tid >> 5;
    int row0 = blockIdx.x * 128;

    for (int i = tid; i < 128 * 32; i += 256) {
        int r = i >> 5, v = i & 31;
        float4 val = make_float4(0.f, 0.f, 0.f, 0.f);
        if (row0 + r < n) val = __ldg(&((const float4*)X)[(size_t)(row0 + r) * 32 + v]);
        val.x = tf32r(val.x); val.y = tf32r(val.y);
        val.z = tf32r(val.z); val.w = tf32r(val.w);
        *(float4*)&sX[r * 132 + v * 4] = val;
    }
    for (int i = tid; i < 128 * (COUT / 4); i += 256) {
        int k = i / (COUT / 4), c4 = i % (COUT / 4);
        float4 wv = __ldg(&((const float4*)W)[(size_t)k * (COUT / 4) + c4]);
        wv.x = tf32r(wv.x); wv.y = tf32r(wv.y);
        wv.z = tf32r(wv.z); wv.w = tf32r(wv.w);
        *(float4*)&sW[k * WS + c4 * 4] = wv;
    }
    __syncthreads();

    float4 acc[NT];
    #pragma unroll
    for (int t = 0; t < NT; t++) acc[t] = make_float4(0.f, 0.f, 0.f, 0.f);
    int qid = lane >> 2, tq = lane & 3;
    int rw = warp * 16;

    #pragma unroll
    for (int kt = 0; kt < 16; kt++) {
        int k0 = kt * 8;
        uint32_t a[4];
        a[0] = __float_as_uint(sX[(rw + qid) * 132 + k0 + tq]);
        a[1] = __float_as_uint(sX[(rw + qid + 8) * 132 + k0 + tq]);
        a[2] = __float_as_uint(sX[(rw + qid) * 132 + k0 + tq + 4]);
        a[3] = __float_as_uint(sX[(rw + qid + 8) * 132 + k0 + tq + 4]);
        #pragma unroll
        for (int nt = 0; nt < NT; nt++) {
            uint32_t bb[2];
            bb[0] = __float_as_uint(sW[(k0 + tq) * WS + nt * 8 + qid]);
            bb[1] = __float_as_uint(sW[(k0 + tq + 4) * WS + nt * 8 + qid]);
            mma_tf32(acc[nt], a, bb);
        }
    }

    int r1 = row0 + rw + qid, r2 = r1 + 8;
    float s1v = (r1 < n) ? __ldg(&s[r1]) : 0.f;
    float s2v = (r2 < n) ? __ldg(&s[r2]) : 0.f;
    #pragma unroll
    for (int nt = 0; nt < NT; nt++) {
        int c = nt * 8 + 2 * tq;
        if (r1 < n)
            *(__half2*)&Y[(size_t)r1 * COUT + c] =
                __floats2half2_rn(s1v * acc[nt].x, s1v * acc[nt].y);
        if (r2 < n)
            *(__half2*)&Y[(size_t)r2 * COUT + c] =
                __floats2half2_rn(s2v * acc[nt].z, s2v * acc[nt].w);
    }
}

// ---------------- fused edge gather + node epilogue ----------------
// h[i] = gelu( isq[i] * (sum_{j in N(i)} msg[j] + msg[i]) + b )
__global__ void k_edgenode128(const int* __restrict__ rp, const int* __restrict__ csr,
                              const float* __restrict__ isq, const __half* __restrict__ msg,
                              const float* __restrict__ b, float* __restrict__ h) {
    int w = (blockIdx.x * blockDim.x + threadIdx.x) >> 5;
    int lane = threadIdx.x & 31;
    if (w >= NN) return;
    int e0 = __ldg(&rp[w]), e1 = __ldg(&rp[w + 1]);
    const uint2* M = (const uint2*)msg;   // 4 halves per lane
    float4 acc = make_float4(0.f, 0.f, 0.f, 0.f);
    acc_h2x2(acc, __ldg(&M[(size_t)w * 32 + lane]));   // self
    int e = e0;
    for (; e + 4 <= e1; e += 4) {
        int s0 = __ldg(&csr[e]),     s1 = __ldg(&csr[e + 1]);
        int s2 = __ldg(&csr[e + 2]), s3 = __ldg(&csr[e + 3]);
        uint2 v0 = __ldg(&M[(size_t)s0 * 32 + lane]);
        uint2 v1 = __ldg(&M[(size_t)s1 * 32 + lane]);
        uint2 v2 = __ldg(&M[(size_t)s2 * 32 + lane]);
        uint2 v3 = __ldg(&M[(size_t)s3 * 32 + lane]);
        acc_h2x2(acc, v0); acc_h2x2(acc, v1);
        acc_h2x2(acc, v2); acc_h2x2(acc, v3);
    }
    for (; e < e1; e++) {
        int s0 = __ldg(&csr[e]);
        acc_h2x2(acc, __ldg(&M[(size_t)s0 * 32 + lane]));
    }
    float sc = __ldg(&isq[w]);
    float4 bb = __ldg(&((const float4*)b)[lane]);
    float4 r;
    r.x = gelu_tanh(sc * acc.x + bb.x);
    r.y = gelu_tanh(sc * acc.y + bb.y);
    r.z = gelu_tanh(sc * acc.z + bb.z);
    r.w = gelu_tanh(sc * acc.w + bb.w);
    ((float4*)h)[(size_t)w * 32 + lane] = r;
}

__global__ void k_edgenode64(const int* __restrict__ rp, const int* __restrict__ csr,
                             const float* __restrict__ isq, const __half* __restrict__ msg,
                             const float* __restrict__ b, float* __restrict__ h) {
    int w = (blockIdx.x * blockDim.x + threadIdx.x) >> 5;
    int lane = threadIdx.x & 31;
    if (w >= NN) return;
    int e0 = __ldg(&rp[w]), e1 = __ldg(&rp[w + 1]);
    const uint32_t* M = (const uint32_t*)msg;  // 2 halves per lane
    float2 acc = make_float2(0.f, 0.f);
    {
        uint32_t v = __ldg(&M[(size_t)w * 32 + lane]);
        float2 f = __half22float2(*reinterpret_cast<__half2*>(&v));
        acc.x += f.x; acc.y += f.y;
    }
    int e = e0;
    for (; e + 4 <= e1; e += 4) {
        int s0 = __ldg(&csr[e]),     s1 = __ldg(&csr[e + 1]);
        int s2 = __ldg(&csr[e + 2]), s3 = __ldg(&csr[e + 3]);
        uint32_t v0 = __ldg(&M[(size_t)s0 * 32 + lane]);
        uint32_t v1 = __ldg(&M[(size_t)s1 * 32 + lane]);
        uint32_t v2 = __ldg(&M[(size_t)s2 * 32 + lane]);
        uint32_t v3 = __ldg(&M[(size_t)s3 * 32 + lane]);
        float2 f0 = __half22float2(*reinterpret_cast<__half2*>(&v0));
        float2 f1 = __half22float2(*reinterpret_cast<__half2*>(&v1));
        float2 f2 = __half22float2(*reinterpret_cast<__half2*>(&v2));
        float2 f3 = __half22float2(*reinterpret_cast<__half2*>(&v3));
        acc.x += f0.x + f1.x + f2.x + f3.x;
        acc.y += f0.y + f1.y + f2.y + f3.y;
    }
    for (; e < e1; e++) {
        uint32_t v = __ldg(&M[(size_t)__ldg(&csr[e]) * 32 + lane]);
        float2 f = __half22float2(*reinterpret_cast<__half2*>(&v));
        acc.x += f.x; acc.y += f.y;
    }
    float sc = __ldg(&isq[w]);
    float2 bb = __ldg(&((const float2*)b)[lane]);
    float2 r;
    r.x = gelu_tanh(sc * acc.x + bb.x);
    r.y = gelu_tanh(sc * acc.y + bb.y);
    ((float2*)h)[(size_t)w * 32 + lane] = r;
}

// ---------------- pooling ----------------
__global__ void k_pool_count(const int* __restrict__ batch, float* __restrict__ cnt) {
    int i = blockIdx.x * blockDim.x + threadIdx.x;
    if (i < NN) atomicAdd(&cnt[batch[i]], 1.0f);
}

__global__ void k_pool_sum(const int* __restrict__ batch, const float* __restrict__ h,
                           float* __restrict__ sums) {
    int i = blockIdx.x * blockDim.x + threadIdx.x;
    if (i >= NN * 16) return;
    int node = i >> 4;
    int v = i & 15;
    int g = __ldg(&batch[node]);
    float4 x = ((const float4*)h)[i];
    red_add_v4(sums + (size_t)g * 64 + (size_t)v * 4, x.x, x.y, x.z, x.w);
}

__global__ void k_pool_fin(const float* __restrict__ sums, const float* __restrict__ cnt,
                           float* __restrict__ out) {
    int i = blockIdx.x * blockDim.x + threadIdx.x;
    if (i >= NG * 64) return;
    float c = fmaxf(cnt[i >> 6], 1.0f);
    out[i] = sums[i] / c;
}

// ---------------- launch ----------------
extern "C" void kernel_launch(void* const* d_in, const int* in_sizes, int n_in,
                              void* d_out, int out_size) {
    const float* x = (const float*)d_in[0];
    const int* ei = (const int*)d_in[1];
    const int* batch = (const int*)d_in[2];
    const float* W0 = (const float*)d_in[3];
    const float* b0 = (const float*)d_in[4];
    const float* W1 = (const float*)d_in[5];
    const float* b1 = (const float*)d_in[6];
    const float* W2 = (const float*)d_in[7];
    const float* b2 = (const float*)d_in[8];
    const int* src = ei;
    const int* dst = ei + NE;

    __half* msg;
    float *bufC, *isq, *sums, *cntf;
    int *cnti, *fill, *rowptr, *tmp, *part, *offs, *csr;
    cudaGetSymbolAddress((void**)&msg, g_msg);
    cudaGetSymbolAddress((void**)&bufC, g_bufC);
    cudaGetSymbolAddress((void**)&isq, g_isq);
    cudaGetSymbolAddress((void**)&cnti, g_cnti);
    cudaGetSymbolAddress((void**)&fill, g_fill);
    cudaGetSymbolAddress((void**)&rowptr, g_rowptr);
    cudaGetSymbolAddress((void**)&tmp, g_tmp);
    cudaGetSymbolAddress((void**)&part, g_part);
    cudaGetSymbolAddress((void**)&offs, g_offs);
    cudaGetSymbolAddress((void**)&csr, g_csr);
    cudaGetSymbolAddress((void**)&sums, g_sums);
    cudaGetSymbolAddress((void**)&cntf, g_cntf);

    const int SM128 = (128 * 132 + 128 * 132) * 4;  // 135168
    const int SM64  = (128 * 132 + 128 * 68) * 4;   // 102400
    cudaFuncSetAttribute(k_gemm_tc<128>, cudaFuncAttributeMaxDynamicSharedMemorySize, SM128);
    cudaFuncSetAttribute(k_gemm_tc<64>, cudaFuncAttributeMaxDynamicSharedMemorySize, SM64);

    // CSR build + degrees
    cudaMemsetAsync(cnti, 0, NN * sizeof(int));
    k_count<<<(NE + 255) / 256, 256>>>(dst, cnti);
    k_isq<<<(NN + 255) / 256, 256>>>(cnti, isq);
    k_scan1<<<SCAN_NB, 1024>>>(cnti, tmp, part);
    k_scan2<<<1, 128>>>(part, offs);
    k_scan3<<<(NN + 255) / 256, 256>>>(tmp, offs, rowptr);
    cudaMemsetAsync(fill, 0, NN * sizeof(int));
    k_fill<<<(NE + 255) / 256, 256>>>(src, dst, rowptr, fill, csr);

    const int GB = (NN + 127) / 128;

    // layer 0
    k_gemm_tc<128><<<GB, 256, SM128>>>(x, W0, isq, msg, NN);
    k_edgenode128<<<(NN * 32 + 255) / 256, 256>>>(rowptr, csr, isq, msg, b0, bufC);
    // layer 1
    k_gemm_tc<128><<<GB, 256, SM128>>>(bufC, W1, isq, msg, NN);
    k_edgenode128<<<(NN * 32 + 255) / 256, 256>>>(rowptr, csr, isq, msg, b1, bufC);
    // layer 2 (out 64)
    k_gemm_tc<64><<<GB, 256, SM64>>>(bufC, W2, isq, msg, NN);
    k_edgenode64<<<(NN * 32 + 255) / 256, 256>>>(rowptr, csr, isq, msg, b2, bufC);

    // pooling
    cudaMemsetAsync(sums, 0, NG * 64 * sizeof(float));
    cudaMemsetAsync(cntf, 0, NG * sizeof(float));
    k_pool_count<<<(NN + 255) / 256, 256>>>(batch, cntf);
    k_pool_sum<<<(NN * 16 + 255) / 256, 256>>>(batch, bufC, sums);
    k_pool_fin<<<(NG * 64 + 255) / 256, 256>>>(sums, cntf, (float*)d_out);
}